// round 2
// baseline (speedup 1.0000x reference)
#include <cuda_runtime.h>
#include <cuda_bf16.h>

// Problem shape (fixed by reference setup_inputs)
#define B_DIM 32
#define C_DIM 512
#define HW    4096            // 64*64
#define KTOP  256             // 0.5 * C
#define NBC   (B_DIM * C_DIM) // 16384

// Scratch (no cudaMalloc allowed)
__device__ float g_ssq[NBC];     // per-(b,c) sum of targets^2 (ranking key)
__device__ float g_ssd[NBC];     // per-(b,c) sum of (in - tgt)^2
__device__ float g_batch[B_DIM];
__device__ unsigned int g_done;  // zero-initialized at module load; reset by last block

// ---------------------------------------------------------------------------
// Kernel 1: one block per PAIR of channels. 256 threads; each thread reads
// 8 float4 per tensor (16 LDG.128 total, front-batched for max MLP).
// Streaming loads (__ldcs) — data has zero reuse, don't pollute L2.
// float4 i in [0,3] belongs to channel c0, i in [4,7] to channel c1.
// ---------------------------------------------------------------------------
__global__ __launch_bounds__(256) void bc_reduce_kernel(
    const float* __restrict__ inp,
    const float* __restrict__ tgt)
{
    const int pair = blockIdx.x;                 // 0 .. NBC/2-1
    const float4* __restrict__ ip =
        reinterpret_cast<const float4*>(inp + (size_t)pair * (2 * HW));
    const float4* __restrict__ tp =
        reinterpret_cast<const float4*>(tgt + (size_t)pair * (2 * HW));

    const int t = threadIdx.x;

    // Front-batch all 16 loads so the compiler issues them as one MLP burst.
    float4 ia[8], ta[8];
#pragma unroll
    for (int i = 0; i < 8; i++) {
        ia[i] = __ldcs(ip + t + i * 256);
        ta[i] = __ldcs(tp + t + i * 256);
    }

    float ssq0 = 0.f, ssd0 = 0.f, ssq1 = 0.f, ssd1 = 0.f;
#pragma unroll
    for (int i = 0; i < 8; i++) {
        float4 a = ia[i];
        float4 b = ta[i];
        float q = 0.f, d = 0.f;
        q = fmaf(b.x, b.x, q);
        q = fmaf(b.y, b.y, q);
        q = fmaf(b.z, b.z, q);
        q = fmaf(b.w, b.w, q);
        float dx = a.x - b.x, dy = a.y - b.y, dz = a.z - b.z, dw = a.w - b.w;
        d = fmaf(dx, dx, d);
        d = fmaf(dy, dy, d);
        d = fmaf(dz, dz, d);
        d = fmaf(dw, dw, d);
        if (i < 4) { ssq0 += q; ssd0 += d; }
        else       { ssq1 += q; ssd1 += d; }
    }

    // warp reduce all four accumulators
#pragma unroll
    for (int off = 16; off > 0; off >>= 1) {
        ssq0 += __shfl_xor_sync(0xFFFFFFFFu, ssq0, off);
        ssd0 += __shfl_xor_sync(0xFFFFFFFFu, ssd0, off);
        ssq1 += __shfl_xor_sync(0xFFFFFFFFu, ssq1, off);
        ssd1 += __shfl_xor_sync(0xFFFFFFFFu, ssd1, off);
    }

    __shared__ float s_q0[8], s_d0[8], s_q1[8], s_d1[8];
    const int warp = t >> 5;
    const int lane = t & 31;
    if (lane == 0) {
        s_q0[warp] = ssq0; s_d0[warp] = ssd0;
        s_q1[warp] = ssq1; s_d1[warp] = ssd1;
    }
    __syncthreads();

    if (warp == 0) {
        float q0 = (lane < 8) ? s_q0[lane] : 0.f;
        float d0 = (lane < 8) ? s_d0[lane] : 0.f;
        float q1 = (lane < 8) ? s_q1[lane] : 0.f;
        float d1 = (lane < 8) ? s_d1[lane] : 0.f;
#pragma unroll
        for (int off = 4; off > 0; off >>= 1) {
            q0 += __shfl_xor_sync(0xFFFFFFFFu, q0, off);
            d0 += __shfl_xor_sync(0xFFFFFFFFu, d0, off);
            q1 += __shfl_xor_sync(0xFFFFFFFFu, q1, off);
            d1 += __shfl_xor_sync(0xFFFFFFFFu, d1, off);
        }
        if (lane == 0) {
            g_ssq[2 * pair]     = q0;
            g_ssd[2 * pair]     = d0;
            g_ssq[2 * pair + 1] = q1;
            g_ssd[2 * pair + 1] = d1;
        }
    }
}

// ---------------------------------------------------------------------------
// Kernel 2 (fused select + final): one block per batch element, 512 threads
// (one per channel). Top-k by rank counting: keep c iff
// #{j : ssq[j] > ssq[c]} < KTOP (exact for distinct random floats).
// Block-reduce kept ssd -> g_batch[b]. Last block to finish sums the 32
// partials IN FIXED ORDER (deterministic), writes the scalar, and resets the
// completion counter so graph replays start clean.
// ---------------------------------------------------------------------------
__global__ __launch_bounds__(512) void select_final_kernel(float* __restrict__ out)
{
    __shared__ float s_norm[C_DIM];
    __shared__ float s_part[16];

    const int b = blockIdx.x;
    const int c = threadIdx.x;

    const float v = g_ssq[b * C_DIM + c];
    s_norm[c] = v;
    __syncthreads();

    int cnt = 0;
#pragma unroll 8
    for (int j = 0; j < C_DIM; j++)
        cnt += (s_norm[j] > v) ? 1 : 0;

    float contrib = (cnt < KTOP) ? g_ssd[b * C_DIM + c] : 0.0f;

#pragma unroll
    for (int off = 16; off > 0; off >>= 1)
        contrib += __shfl_xor_sync(0xFFFFFFFFu, contrib, off);

    const int warp = c >> 5;
    const int lane = c & 31;
    if (lane == 0) s_part[warp] = contrib;
    __syncthreads();

    __shared__ bool s_last;
    if (warp == 0) {
        float x = (lane < 16) ? s_part[lane] : 0.0f;
#pragma unroll
        for (int off = 8; off > 0; off >>= 1)
            x += __shfl_xor_sync(0xFFFFFFFFu, x, off);
        if (lane == 0) {
            g_batch[b] = x;
            __threadfence();
            unsigned int prev = atomicAdd(&g_done, 1u);
            s_last = (prev == B_DIM - 1);
        }
    }
    __syncthreads();

    if (s_last && c == 0) {
        float total = 0.0f;
#pragma unroll
        for (int i = 0; i < B_DIM; i++)
            total += g_batch[i];
        out[0] = total / ((float)HW * (float)(B_DIM * KTOP));
        g_done = 0;   // reset for the next graph replay
    }
}

extern "C" void kernel_launch(void* const* d_in, const int* in_sizes, int n_in,
                              void* d_out, int out_size)
{
    const float* inputs  = (const float*)d_in[0];
    const float* targets = (const float*)d_in[1];
    float* out = (float*)d_out;

    bc_reduce_kernel<<<NBC / 2, 256>>>(inputs, targets);
    select_final_kernel<<<B_DIM, C_DIM>>>(out);
}

// round 3
// speedup vs baseline: 1.0481x; 1.0481x over previous
#include <cuda_runtime.h>
#include <cuda_bf16.h>

// Problem shape (fixed by reference setup_inputs)
#define B_DIM 32
#define C_DIM 512
#define HW    4096            // 64*64
#define KTOP  256             // 0.5 * C
#define NBC   (B_DIM * C_DIM) // 16384
#define SEL_BLOCKS 128        // 32 batches x 4 channel groups

// Scratch (no cudaMalloc allowed)
__device__ float g_ssq[NBC];        // per-(b,c) sum of targets^2 (ranking key)
__device__ float g_ssd[NBC];        // per-(b,c) sum of (in - tgt)^2
__device__ float g_part[SEL_BLOCKS];
__device__ unsigned int g_done;     // zeroed at load; reset by last block each run

// ---------------------------------------------------------------------------
// Kernel 1 (UNCHANGED from R1 — known 79.7us @ 85.7% DRAM): one block per
// (b,c). 256 threads, each reads 4x float4 from each tensor, computes
// ssq(target) and ssd, block-reduces both. Pure streaming, at the HBM wall.
// ---------------------------------------------------------------------------
__global__ __launch_bounds__(256) void bc_reduce_kernel(
    const float* __restrict__ inp,
    const float* __restrict__ tgt)
{
    const int bc = blockIdx.x;
    const float4* __restrict__ ip =
        reinterpret_cast<const float4*>(inp + (size_t)bc * HW);
    const float4* __restrict__ tp =
        reinterpret_cast<const float4*>(tgt + (size_t)bc * HW);

    const int t = threadIdx.x;

    float ssq = 0.0f;
    float ssd = 0.0f;

#pragma unroll
    for (int i = 0; i < 4; i++) {
        float4 a = ip[t + i * 256];
        float4 b = tp[t + i * 256];
        ssq = fmaf(b.x, b.x, ssq);
        ssq = fmaf(b.y, b.y, ssq);
        ssq = fmaf(b.z, b.z, ssq);
        ssq = fmaf(b.w, b.w, ssq);
        float dx = a.x - b.x;
        float dy = a.y - b.y;
        float dz = a.z - b.z;
        float dw = a.w - b.w;
        ssd = fmaf(dx, dx, ssd);
        ssd = fmaf(dy, dy, ssd);
        ssd = fmaf(dz, dz, ssd);
        ssd = fmaf(dw, dw, ssd);
    }

#pragma unroll
    for (int off = 16; off > 0; off >>= 1) {
        ssq += __shfl_xor_sync(0xFFFFFFFFu, ssq, off);
        ssd += __shfl_xor_sync(0xFFFFFFFFu, ssd, off);
    }

    __shared__ float s_ssq[8];
    __shared__ float s_ssd[8];
    const int warp = t >> 5;
    const int lane = t & 31;
    if (lane == 0) {
        s_ssq[warp] = ssq;
        s_ssd[warp] = ssd;
    }
    __syncthreads();

    if (warp == 0) {
        float q = (lane < 8) ? s_ssq[lane] : 0.0f;
        float d = (lane < 8) ? s_ssd[lane] : 0.0f;
#pragma unroll
        for (int off = 4; off > 0; off >>= 1) {
            q += __shfl_xor_sync(0xFFFFFFFFu, q, off);
            d += __shfl_xor_sync(0xFFFFFFFFu, d, off);
        }
        if (lane == 0) {
            g_ssq[bc] = q;
            g_ssd[bc] = d;
        }
    }
}

// ---------------------------------------------------------------------------
// Kernel 2: fused select + final. Grid = 32 batches x 4 channel groups,
// 128 threads/block (1 wave over 128 SMs, 1 warp/SMSP). Each block loads all
// 512 norms of its batch into SMEM; each thread rank-counts its one channel
// against the full 512 using float4 LDS (128 iters x 4 compares, broadcast).
// Kept ssd -> block partial -> g_part. Last finished block reduces the 128
// partials in a fixed tree (deterministic) and writes the scalar.
// ---------------------------------------------------------------------------
__global__ __launch_bounds__(128) void select_final_kernel(float* __restrict__ out)
{
    __shared__ float4 s_norm4[C_DIM / 4];   // 512 norms as 128 float4
    __shared__ float  s_p[4];
    __shared__ bool   s_last;

    const int b = blockIdx.x >> 2;     // batch
    const int g = blockIdx.x & 3;      // channel group (128 channels)
    const int t = threadIdx.x;
    const int warp = t >> 5;
    const int lane = t & 31;

    // cooperative load of this batch's 512 ranking keys
    s_norm4[t] = reinterpret_cast<const float4*>(g_ssq + b * C_DIM)[t];
    __syncthreads();

    const int c = g * 128 + t;         // this thread's channel
    const float v = reinterpret_cast<const float*>(s_norm4)[c];

    int cnt = 0;
#pragma unroll 4
    for (int j = 0; j < C_DIM / 4; j++) {
        float4 n = s_norm4[j];         // broadcast, conflict-free
        cnt += (n.x > v) ? 1 : 0;
        cnt += (n.y > v) ? 1 : 0;
        cnt += (n.z > v) ? 1 : 0;
        cnt += (n.w > v) ? 1 : 0;
    }

    float contrib = (cnt < KTOP) ? g_ssd[b * C_DIM + c] : 0.0f;

#pragma unroll
    for (int off = 16; off > 0; off >>= 1)
        contrib += __shfl_xor_sync(0xFFFFFFFFu, contrib, off);
    if (lane == 0) s_p[warp] = contrib;
    __syncthreads();

    if (t == 0) {
        float x = (s_p[0] + s_p[1]) + (s_p[2] + s_p[3]);
        g_part[blockIdx.x] = x;
        __threadfence();
        unsigned int prev = atomicAdd(&g_done, 1u);
        s_last = (prev == SEL_BLOCKS - 1);
    }
    __syncthreads();

    if (s_last) {
        __threadfence();               // acquire: make all g_part writes visible
        float x = g_part[t];           // 128 partials, one per thread
#pragma unroll
        for (int off = 16; off > 0; off >>= 1)
            x += __shfl_xor_sync(0xFFFFFFFFu, x, off);

        __shared__ float s_f[4];
        if (lane == 0) s_f[warp] = x;
        __syncthreads();
        if (t == 0) {
            float total = (s_f[0] + s_f[1]) + (s_f[2] + s_f[3]);
            out[0] = total / ((float)HW * (float)(B_DIM * KTOP));
            g_done = 0;                // reset for next graph replay
        }
    }
}

extern "C" void kernel_launch(void* const* d_in, const int* in_sizes, int n_in,
                              void* d_out, int out_size)
{
    const float* inputs  = (const float*)d_in[0];
    const float* targets = (const float*)d_in[1];
    float* out = (float*)d_out;

    bc_reduce_kernel<<<NBC, 256>>>(inputs, targets);
    select_final_kernel<<<SEL_BLOCKS, 128>>>(out);
}